// round 15
// baseline (speedup 1.0000x reference)
#include <cuda_runtime.h>
#include <cuda_fp16.h>

#define N_NODES 400000
#define N_EDGES 1600000
#define N_GRAPHS 10000
#define H 64
#define NODE_DIM 74
#define EDGE_DIM 13
#define WPB 8
#define CT 5         // 16-row tiles per warp in MMA kernels

#define CGRID  (N_EDGES / (WPB * CT * 16))   // 2500
#define H0GRID (N_EDGES / (WPB * 16))        // 12500
#define PGRID  (N_NODES / (WPB * CT * 16))   // 625

// ---------------- device scratch ----------------
__device__ __half g_node[(size_t)N_NODES * H];
__device__ __half g_P[(size_t)N_NODES * H];
__device__ __half g_h0[(size_t)N_EDGES * H];
__device__ __half g_hA[(size_t)N_EDGES * H];
__device__ __half g_hB[(size_t)N_EDGES * H];
__device__ __half g_aggA[(size_t)N_NODES * H];   // fp16 segment sums (f16x2 atomics)
__device__ __half g_aggB[(size_t)N_NODES * H];
__device__ float g_gpool[(size_t)N_GRAPHS * H];
__device__ float g_Wc[EDGE_DIM * H];
__device__ float g_bc[H];

__device__ __forceinline__ float lrelu(float v) { return fmaxf(v, 0.01f * v); }

__device__ __forceinline__ void red_h2v(__half* p, __half2 hv) {
    asm volatile("red.global.add.noftz.f16x2 [%0], %1;"
                 :: "l"(p), "r"(*(unsigned*)&hv) : "memory");
}

#define LDMX4(r0, r1, r2, r3, gaddr)                                          \
    asm volatile("ldmatrix.sync.aligned.m8n8.x4.shared.b16 {%0,%1,%2,%3}, [%4];" \
                 : "=r"(r0), "=r"(r1), "=r"(r2), "=r"(r3) : "r"(gaddr))
#define LDMX4T(r0, r1, r2, r3, gaddr)                                         \
    asm volatile("ldmatrix.sync.aligned.m8n8.x4.trans.shared.b16 {%0,%1,%2,%3}, [%4];" \
                 : "=r"(r0), "=r"(r1), "=r"(r2), "=r"(r3) : "r"(gaddr))
#define MMA16816(acc, a0, a1, a2, a3, b0, b1)                                 \
    asm volatile("mma.sync.aligned.m16n8k16.row.col.f32.f16.f16.f32 "         \
                 "{%0,%1,%2,%3}, {%4,%5,%6,%7}, {%8,%9}, {%0,%1,%2,%3};"      \
                 : "+f"(acc[0]), "+f"(acc[1]), "+f"(acc[2]), "+f"(acc[3])     \
                 : "r"(a0), "r"(a1), "r"(a2), "r"(a3), "r"(b0), "r"(b1))

// ---------------- prep: fold edge projection through Wi ----------------
__global__ void prep_kernel(const float* __restrict__ We, const float* __restrict__ be,
                            const float* __restrict__ Wi, const float* __restrict__ bi,
                            float* __restrict__ Wc, float* __restrict__ bc) {
    int tid = blockIdx.x * blockDim.x + threadIdx.x;
    if (tid < EDGE_DIM * H) {
        int d = tid >> 6, j = tid & 63;
        float s = 0.f;
        #pragma unroll 8
        for (int k = 0; k < H; k++) s += We[d * H + k] * Wi[(H + k) * H + j];
        Wc[tid] = s;
    }
    if (tid < H) {
        float s = bi[tid];
        #pragma unroll 8
        for (int k = 0; k < H; k++) s += be[k] * Wi[(H + k) * H + tid];
        bc[tid] = s;
    }
}

// ---------------- node projection via HMMA (K=74 padded to 80) ----------------
#define LDA 88
__global__ __launch_bounds__(256) void node_proj_mma_kernel(
    const float* __restrict__ nf, const float* __restrict__ Wn,
    const float* __restrict__ bn, __half* __restrict__ node) {
    __shared__ __align__(16) __half sW[80 * 72];
    __shared__ __align__(16) __half sT[8][16 * LDA];
    __shared__ float sb[64];

    int tid = threadIdx.x;
    for (int idx = tid; idx < 80 * 64; idx += 256) {
        int k = idx >> 6, n = idx & 63;
        sW[k * 72 + n] = (k < NODE_DIM) ? __float2half_rn(Wn[k * H + n]) : __half(0.f);
    }
    if (tid < 64) sb[tid] = bn[tid];
    __syncthreads();
    int warp = tid >> 5, lane = tid & 31;

    unsigned bfr[8][5][2];
    #pragma unroll
    for (int nt = 0; nt < 8; nt++) {
        #pragma unroll
        for (int kh = 0; kh < 2; kh++) {
            unsigned r0, r1, r2, r3;
            unsigned addr = (unsigned)__cvta_generic_to_shared(&sW[(kh * 32 + lane) * 72 + nt * 8]);
            LDMX4T(r0, r1, r2, r3, addr);
            bfr[nt][kh * 2][0] = r0;     bfr[nt][kh * 2][1] = r1;
            bfr[nt][kh * 2 + 1][0] = r2; bfr[nt][kh * 2 + 1][1] = r3;
        }
        unsigned r0, r1;
        unsigned addr = (unsigned)__cvta_generic_to_shared(&sW[(64 + (lane & 15)) * 72 + nt * 8]);
        asm volatile("ldmatrix.sync.aligned.m8n8.x2.trans.shared.b16 {%0,%1}, [%2];"
                     : "=r"(r0), "=r"(r1) : "r"(addr));
        bfr[nt][4][0] = r0; bfr[nt][4][1] = r1;
    }

    __half* myT = sT[warp];
    for (int idx = lane; idx < 16 * 3; idx += 32) {
        int r = idx / 3, c = 74 + (idx % 3) * 2;
        *(__half2*)&myT[r * LDA + c] = __floats2half2_rn(0.f, 0.f);
    }
    __syncwarp();

    int base = ((blockIdx.x * 8 + warp) * CT) * 16;
    int am = lane >> 3;
    int arow = (am & 1) * 8 + (lane & 7);
    int acol0 = (am >> 1) * 8;

    for (int t = 0; t < CT; t++) {
        int nb = base + t * 16;
        #pragma unroll
        for (int i = 0; i < 16; i++) {
            const float* row = nf + (size_t)(nb + i) * NODE_DIM;
            float2 f = *(const float2*)&row[2 * lane];
            *(__half2*)&myT[i * LDA + 2 * lane] = __floats2half2_rn(f.x, f.y);
            if (lane < 5) {
                float2 g = *(const float2*)&row[64 + 2 * lane];
                *(__half2*)&myT[i * LDA + 64 + 2 * lane] = __floats2half2_rn(g.x, g.y);
            }
        }
        __syncwarp();
        float acc[8][4];
        #pragma unroll
        for (int nt = 0; nt < 8; nt++) { acc[nt][0]=0.f; acc[nt][1]=0.f; acc[nt][2]=0.f; acc[nt][3]=0.f; }
        #pragma unroll
        for (int kt = 0; kt < 5; kt++) {
            unsigned a0, a1, a2, a3;
            unsigned addr = (unsigned)__cvta_generic_to_shared(&myT[arow * LDA + kt * 16 + acol0]);
            LDMX4(a0, a1, a2, a3, addr);
            #pragma unroll
            for (int nt = 0; nt < 8; nt++)
                MMA16816(acc[nt], a0, a1, a2, a3, bfr[nt][kt][0], bfr[nt][kt][1]);
        }
        __syncwarp();
        int qrow = lane >> 2, qc = (lane & 3) * 2;
        #pragma unroll
        for (int nt = 0; nt < 8; nt++) {
            float b0 = sb[nt * 8 + qc], b1 = sb[nt * 8 + qc + 1];
            *(__half2*)&myT[qrow * LDA + nt * 8 + qc]       = __floats2half2_rn(acc[nt][0] + b0, acc[nt][1] + b1);
            *(__half2*)&myT[(qrow + 8) * LDA + nt * 8 + qc] = __floats2half2_rn(acc[nt][2] + b0, acc[nt][3] + b1);
        }
        __syncwarp();
        #pragma unroll
        for (int i = 0; i < 16; i++)
            *(__half2*)&node[(nb + i) * 64 + 2 * lane] = *(__half2*)&myT[i * LDA + 2 * lane];
        __syncwarp();
    }
}

// ---------------- P = node @ Wi_top (dense fp16 MMA GEMM) ----------------
__global__ __launch_bounds__(256) void pmma_kernel(
    const __half* __restrict__ node, const float* __restrict__ Wi,
    __half* __restrict__ P) {
    __shared__ __align__(16) __half sW[64 * 72];
    __shared__ __align__(16) __half sT[8][16 * 72];
    int tid = threadIdx.x;
    for (int idx = tid; idx < 64 * 64; idx += 256) {
        int k = idx >> 6, n = idx & 63;
        sW[k * 72 + n] = __float2half_rn(Wi[k * H + n]);
    }
    __syncthreads();
    int warp = tid >> 5, lane = tid & 31;

    unsigned bfr[8][4][2];
    #pragma unroll
    for (int nt = 0; nt < 8; nt++) {
        #pragma unroll
        for (int kh = 0; kh < 2; kh++) {
            unsigned r0, r1, r2, r3;
            unsigned addr = (unsigned)__cvta_generic_to_shared(&sW[(kh * 32 + lane) * 72 + nt * 8]);
            LDMX4T(r0, r1, r2, r3, addr);
            bfr[nt][kh * 2][0] = r0;     bfr[nt][kh * 2][1] = r1;
            bfr[nt][kh * 2 + 1][0] = r2; bfr[nt][kh * 2 + 1][1] = r3;
        }
    }
    __half* myT = sT[warp];
    int base = ((blockIdx.x * 8 + warp) * CT) * 16;
    int am = lane >> 3;
    int arow = (am & 1) * 8 + (lane & 7);
    int acol0 = (am >> 1) * 8;

    for (int t = 0; t < CT; t++) {
        int nb = base + t * 16;
        #pragma unroll
        for (int i = 0; i < 16; i++)
            *(__half2*)&myT[i * 72 + 2 * lane] = *(const __half2*)&node[(nb + i) * 64 + 2 * lane];
        __syncwarp();
        float acc[8][4];
        #pragma unroll
        for (int nt = 0; nt < 8; nt++) { acc[nt][0]=0.f; acc[nt][1]=0.f; acc[nt][2]=0.f; acc[nt][3]=0.f; }
        #pragma unroll
        for (int kt = 0; kt < 4; kt++) {
            unsigned a0, a1, a2, a3;
            unsigned addr = (unsigned)__cvta_generic_to_shared(&myT[arow * 72 + kt * 16 + acol0]);
            LDMX4(a0, a1, a2, a3, addr);
            #pragma unroll
            for (int nt = 0; nt < 8; nt++)
                MMA16816(acc[nt], a0, a1, a2, a3, bfr[nt][kt][0], bfr[nt][kt][1]);
        }
        __syncwarp();
        int qrow = lane >> 2, qc = (lane & 3) * 2;
        #pragma unroll
        for (int nt = 0; nt < 8; nt++) {
            *(__half2*)&myT[qrow * 72 + nt * 8 + qc]       = __floats2half2_rn(acc[nt][0], acc[nt][1]);
            *(__half2*)&myT[(qrow + 8) * 72 + nt * 8 + qc] = __floats2half2_rn(acc[nt][2], acc[nt][3]);
        }
        __syncwarp();
        #pragma unroll
        for (int i = 0; i < 16; i++)
            *(__half2*)&P[(nb + i) * 64 + 2 * lane] = *(__half2*)&myT[i * 72 + 2 * lane];
        __syncwarp();
    }
}

// ---------------- h0_lite: h0 = lrelu(P[src] + ef@Wc + bc), scatter fp16 agg ----------------
__global__ __launch_bounds__(256, 4) void h0_lite_kernel(
    const __half* __restrict__ P, const float* __restrict__ ef,
    const int* __restrict__ src, const int* __restrict__ dst,
    const float* __restrict__ Wc, const float* __restrict__ bc,
    __half* __restrict__ h0, __half* __restrict__ agg_out) {
    __shared__ float sEf[WPB][16 * EDGE_DIM];
    int tid = threadIdx.x, warp = tid >> 5, lane = tid & 31;
    int eb = (blockIdx.x * WPB + warp) * 16;

    float2 wc[EDGE_DIM];
    #pragma unroll
    for (int d = 0; d < EDGE_DIM; d++) wc[d] = *(const float2*)&Wc[d * H + 2 * lane];
    float2 bc2 = *(const float2*)&bc[2 * lane];

    float* myEf = sEf[warp];
    for (int idx = lane; idx < 16 * EDGE_DIM; idx += 32)
        myEf[idx] = ef[(size_t)eb * EDGE_DIM + idx];
    int sidx = src[eb + (lane & 15)];
    int didx = dst[eb + (lane & 15)];
    __syncwarp();

    #pragma unroll
    for (int i = 0; i < 16; i++) {
        int s = __shfl_sync(0xffffffffu, sidx, i);
        int d = __shfl_sync(0xffffffffu, didx, i);
        float2 p2 = __half22float2(*(const __half2*)&P[s * 64 + 2 * lane]);
        float a0 = p2.x + bc2.x, a1 = p2.y + bc2.y;
        #pragma unroll
        for (int k = 0; k < EDGE_DIM; k++) {
            float e = myEf[i * EDGE_DIM + k];
            a0 += e * wc[k].x; a1 += e * wc[k].y;
        }
        __half2 hv = __floats2half2_rn(lrelu(a0), lrelu(a1));
        *(__half2*)&h0[(size_t)(eb + i) * 64 + 2 * lane] = hv;
        red_h2v(&agg_out[d * 64 + 2 * lane], hv);
    }
}

// ---------------- conv layer: HMMA, fp16 agg gather + scatter ----------------
__global__ __launch_bounds__(256, 3) void conv_mma_kernel(
    const float* __restrict__ W, const float* __restrict__ bias,
    const int* __restrict__ src, const int* __restrict__ dst,
    const __half* __restrict__ agg_in, const __half* __restrict__ h_in,
    const __half* __restrict__ h0, __half* __restrict__ h_out,
    __half* __restrict__ agg_out) {
    __shared__ __align__(16) __half sW[64 * 72];
    __shared__ __align__(16) __half sT[8][16 * 72];

    int tid = threadIdx.x;
    for (int idx = tid; idx < 64 * 64; idx += 256) {
        int k = idx >> 6, n = idx & 63;
        sW[k * 72 + n] = __float2half_rn(W[idx]);
    }
    __syncthreads();
    int warp = tid >> 5, lane = tid & 31;
    float2 bias2 = *(const float2*)&bias[2 * lane];

    __half* myT = sT[warp];
    int base = ((blockIdx.x * 8 + warp) * CT) * 16;
    int am = lane >> 3;
    int arow = (am & 1) * 8 + (lane & 7);
    int acol0 = (am >> 1) * 8;

    for (int t = 0; t < CT; t++) {
        int eb = base + t * 16;
        int sidx = src[eb + (lane & 15)];
        int didx = dst[eb + (lane & 15)];
        #pragma unroll
        for (int i = 0; i < 16; i++) {
            int s = __shfl_sync(0xffffffffu, sidx, i);
            int r = (eb + i) ^ 1;
            float2 a = __half22float2(*(const __half2*)&agg_in[s * 64 + 2 * lane]);
            float2 hf = __half22float2(*(const __half2*)&h_in[r * 64 + 2 * lane]);
            *(__half2*)&myT[i * 72 + 2 * lane] = __floats2half2_rn(a.x - hf.x, a.y - hf.y);
        }
        __syncwarp();
        float acc[8][4];
        #pragma unroll
        for (int nt = 0; nt < 8; nt++) { acc[nt][0]=0.f; acc[nt][1]=0.f; acc[nt][2]=0.f; acc[nt][3]=0.f; }
        #pragma unroll
        for (int kh = 0; kh < 2; kh++) {
            unsigned a00, a01, a02, a03, a10, a11, a12, a13;
            unsigned addr0 = (unsigned)__cvta_generic_to_shared(&myT[arow * 72 + (2 * kh) * 16 + acol0]);
            LDMX4(a00, a01, a02, a03, addr0);
            unsigned addr1 = (unsigned)__cvta_generic_to_shared(&myT[arow * 72 + (2 * kh + 1) * 16 + acol0]);
            LDMX4(a10, a11, a12, a13, addr1);
            #pragma unroll
            for (int nt = 0; nt < 8; nt++) {
                unsigned b0, b1, b2, b3;
                unsigned addrB = (unsigned)__cvta_generic_to_shared(&sW[(kh * 32 + lane) * 72 + nt * 8]);
                LDMX4T(b0, b1, b2, b3, addrB);
                MMA16816(acc[nt], a00, a01, a02, a03, b0, b1);
                MMA16816(acc[nt], a10, a11, a12, a13, b2, b3);
            }
        }
        __syncwarp();
        int qrow = lane >> 2, qc = (lane & 3) * 2;
        #pragma unroll
        for (int nt = 0; nt < 8; nt++) {
            *(__half2*)&myT[qrow * 72 + nt * 8 + qc]       = __floats2half2_rn(acc[nt][0], acc[nt][1]);
            *(__half2*)&myT[(qrow + 8) * 72 + nt * 8 + qc] = __floats2half2_rn(acc[nt][2], acc[nt][3]);
        }
        __syncwarp();
        #pragma unroll
        for (int i = 0; i < 16; i++) {
            int d = __shfl_sync(0xffffffffu, didx, i);
            float2 m2  = __half22float2(*(const __half2*)&myT[i * 72 + 2 * lane]);
            float2 h0f = __half22float2(*(const __half2*)&h0[(eb + i) * 64 + 2 * lane]);
            __half2 hv = __floats2half2_rn(lrelu(h0f.x + bias2.x + m2.x),
                                           lrelu(h0f.y + bias2.y + m2.y));
            *(__half2*)&h_out[(eb + i) * 64 + 2 * lane] = hv;
            red_h2v(&agg_out[d * 64 + 2 * lane], hv);
        }
        __syncwarp();
    }
}

// ---------------- readout via HMMA: gpool[gid[n]] += lrelu([node,agg]@Wa + ba) ----------------
__global__ __launch_bounds__(256, 3) void readout_mma_kernel(
    const __half* __restrict__ node, const __half* __restrict__ agg,
    const float* __restrict__ Wa, const float* __restrict__ ba,
    const int* __restrict__ gid, float* __restrict__ gpool) {
    __shared__ __align__(16) __half sW[128 * 72];
    __shared__ __align__(16) __half sT[8][16 * 72];
    __shared__ float sba[64];

    int tid = threadIdx.x;
    for (int idx = tid; idx < 128 * 64; idx += 256) {
        int k = idx >> 6, n = idx & 63;
        sW[k * 72 + n] = __float2half_rn(Wa[k * H + n]);
    }
    if (tid < 64) sba[tid] = ba[tid];
    __syncthreads();
    int warp = tid >> 5, lane = tid & 31;

    __half* myT = sT[warp];
    int base = ((blockIdx.x * 8 + warp) * CT) * 16;
    int am = lane >> 3;
    int arow = (am & 1) * 8 + (lane & 7);
    int acol0 = (am >> 1) * 8;

    for (int t = 0; t < CT; t++) {
        int nb = base + t * 16;
        int gidx = gid[nb + (lane & 15)];
        float acc[8][4];
        #pragma unroll
        for (int nt = 0; nt < 8; nt++) { acc[nt][0]=0.f; acc[nt][1]=0.f; acc[nt][2]=0.f; acc[nt][3]=0.f; }

        #pragma unroll
        for (int stage = 0; stage < 2; stage++) {
            #pragma unroll
            for (int i = 0; i < 16; i++) {
                const __half* in = stage ? &agg[(nb + i) * 64] : &node[(nb + i) * 64];
                *(__half2*)&myT[i * 72 + 2 * lane] = *(const __half2*)&in[2 * lane];
            }
            __syncwarp();
            #pragma unroll
            for (int kh = 0; kh < 2; kh++) {
                unsigned a00, a01, a02, a03, a10, a11, a12, a13;
                unsigned addr0 = (unsigned)__cvta_generic_to_shared(&myT[arow * 72 + (2 * kh) * 16 + acol0]);
                LDMX4(a00, a01, a02, a03, addr0);
                unsigned addr1 = (unsigned)__cvta_generic_to_shared(&myT[arow * 72 + (2 * kh + 1) * 16 + acol0]);
                LDMX4(a10, a11, a12, a13, addr1);
                #pragma unroll
                for (int nt = 0; nt < 8; nt++) {
                    unsigned b0, b1, b2, b3;
                    unsigned addrB = (unsigned)__cvta_generic_to_shared(
                        &sW[(stage * 64 + kh * 32 + lane) * 72 + nt * 8]);
                    LDMX4T(b0, b1, b2, b3, addrB);
                    MMA16816(acc[nt], a00, a01, a02, a03, b0, b1);
                    MMA16816(acc[nt], a10, a11, a12, a13, b2, b3);
                }
            }
            __syncwarp();
        }
        int qrow = lane >> 2, qc = (lane & 3) * 2;
        int g0 = __shfl_sync(0xffffffffu, gidx, qrow);
        int g1 = __shfl_sync(0xffffffffu, gidx, qrow + 8);
        #pragma unroll
        for (int nt = 0; nt < 8; nt++) {
            float b0 = sba[nt * 8 + qc], b1 = sba[nt * 8 + qc + 1];
            float o00 = lrelu(acc[nt][0] + b0), o01 = lrelu(acc[nt][1] + b1);
            float o10 = lrelu(acc[nt][2] + b0), o11 = lrelu(acc[nt][3] + b1);
            asm volatile("red.global.add.v2.f32 [%0], {%1, %2};"
                         :: "l"(&gpool[g0 * 64 + nt * 8 + qc]), "f"(o00), "f"(o01) : "memory");
            asm volatile("red.global.add.v2.f32 [%0], {%1, %2};"
                         :: "l"(&gpool[g1 * 64 + nt * 8 + qc]), "f"(o10), "f"(o11) : "memory");
        }
    }
}

// ---------------- head ----------------
__global__ __launch_bounds__(256) void head_kernel(
    const float* __restrict__ g, const float* __restrict__ W1,
    const float* __restrict__ b1, const float* __restrict__ W2,
    const float* __restrict__ b2, float* __restrict__ out) {
    __shared__ float2 sW[H * 32];
    __shared__ float sb[H];
    __shared__ float sW2[H];
    for (int idx = threadIdx.x; idx < H * 32; idx += 256) {
        int k = idx >> 5, j = idx & 31;
        sW[idx] = make_float2(W1[k * H + j], W1[k * H + j + 32]);
    }
    if (threadIdx.x < H) { sb[threadIdx.x] = b1[threadIdx.x]; sW2[threadIdx.x] = W2[threadIdx.x]; }
    __syncthreads();
    int warp = threadIdx.x >> 5, lane = threadIdx.x & 31;
    int gi = blockIdx.x * 8 + warp;
    const float* row = g + gi * H;
    float f0 = row[lane], f1 = row[lane + 32];
    float a0 = sb[lane], a1 = sb[lane + 32];
    #pragma unroll
    for (int k = 0; k < H; k++) {
        float fk = __shfl_sync(0xffffffffu, (k < 32 ? f0 : f1), k & 31);
        float2 w = sW[k * 32 + lane];
        a0 += fk * w.x; a1 += fk * w.y;
    }
    a0 = lrelu(a0); a1 = lrelu(a1);
    float p = a0 * sW2[lane] + a1 * sW2[lane + 32];
    #pragma unroll
    for (int o = 16; o; o >>= 1) p += __shfl_xor_sync(0xffffffffu, p, o);
    if (lane == 0) out[gi] = p + b2[0];
}

// ---------------- launch ----------------
extern "C" void kernel_launch(void* const* d_in, const int* in_sizes, int n_in,
                              void* d_out, int out_size) {
    const float* node_feats = (const float*)d_in[0];
    const float* edge_feats = (const float*)d_in[1];
    const int*   src        = (const int*)d_in[2];
    const int*   dst        = (const int*)d_in[3];
    const int*   gid        = (const int*)d_in[4];
    const float* Wn = (const float*)d_in[5];
    const float* bn = (const float*)d_in[6];
    const float* We = (const float*)d_in[7];
    const float* be = (const float*)d_in[8];
    const float* Wi = (const float*)d_in[9];
    const float* bi = (const float*)d_in[10];
    const float* Wa = (const float*)d_in[11];
    const float* ba = (const float*)d_in[12];
    const float* Wl = (const float*)d_in[13];
    const float* bl = (const float*)d_in[14];
    const float* W1 = (const float*)d_in[15];
    const float* b1 = (const float*)d_in[16];
    const float* W2 = (const float*)d_in[17];
    const float* b2 = (const float*)d_in[18];
    float* out = (float*)d_out;

    __half *p_node, *p_P, *p_h0, *p_hA, *p_hB, *p_aggA, *p_aggB;
    float *p_gpool, *p_Wc, *p_bc;
    cudaGetSymbolAddress((void**)&p_node, g_node);
    cudaGetSymbolAddress((void**)&p_P, g_P);
    cudaGetSymbolAddress((void**)&p_h0, g_h0);
    cudaGetSymbolAddress((void**)&p_hA, g_hA);
    cudaGetSymbolAddress((void**)&p_hB, g_hB);
    cudaGetSymbolAddress((void**)&p_aggA, g_aggA);
    cudaGetSymbolAddress((void**)&p_aggB, g_aggB);
    cudaGetSymbolAddress((void**)&p_gpool, g_gpool);
    cudaGetSymbolAddress((void**)&p_Wc, g_Wc);
    cudaGetSymbolAddress((void**)&p_bc, g_bc);

    const size_t aggBytes = (size_t)N_NODES * H * sizeof(__half);

    prep_kernel<<<4, 256>>>(We, be, Wi, bi, p_Wc, p_bc);
    node_proj_mma_kernel<<<PGRID, 256>>>(node_feats, Wn, bn, p_node);
    pmma_kernel<<<PGRID, 256>>>(p_node, Wi, p_P);

    cudaMemsetAsync(p_aggA, 0, aggBytes);
    h0_lite_kernel<<<H0GRID, 256>>>(p_P, edge_feats, src, dst, p_Wc, p_bc,
                                    p_h0, p_aggA);

    cudaMemsetAsync(p_aggB, 0, aggBytes);
    conv_mma_kernel<<<CGRID, 256>>>(Wl + 0 * H * H, bl + 0 * H, src, dst,
                                    p_aggA, p_h0, p_h0, p_hA, p_aggB);
    cudaMemsetAsync(p_aggA, 0, aggBytes);
    conv_mma_kernel<<<CGRID, 256>>>(Wl + 1 * H * H, bl + 1 * H, src, dst,
                                    p_aggB, p_hA, p_h0, p_hB, p_aggA);
    cudaMemsetAsync(p_aggB, 0, aggBytes);
    conv_mma_kernel<<<CGRID, 256>>>(Wl + 2 * H * H, bl + 2 * H, src, dst,
                                    p_aggA, p_hB, p_h0, p_hA, p_aggB);
    cudaMemsetAsync(p_aggA, 0, aggBytes);
    conv_mma_kernel<<<CGRID, 256>>>(Wl + 3 * H * H, bl + 3 * H, src, dst,
                                    p_aggB, p_hA, p_h0, p_hB, p_aggA);

    cudaMemsetAsync(p_gpool, 0, (size_t)N_GRAPHS * H * sizeof(float));
    readout_mma_kernel<<<PGRID, 256>>>(p_node, p_aggA, Wa, ba, gid, p_gpool);
    head_kernel<<<N_GRAPHS / 8, 256>>>(p_gpool, W1, b1, W2, b2, out);
}

// round 16
// speedup vs baseline: 1.2025x; 1.2025x over previous
#include <cuda_runtime.h>
#include <cuda_fp16.h>

#define N_NODES 400000
#define N_EDGES 1600000
#define N_GRAPHS 10000
#define H 64
#define NODE_DIM 74
#define EDGE_DIM 13
#define WPB 8
#define CT 5         // 16-row tiles per warp in MMA kernels

#define CGRID  (N_EDGES / (WPB * CT * 16))   // 2500
#define H0GRID (N_EDGES / (WPB * 16))        // 12500
#define PGRID  (N_NODES / (WPB * CT * 16))   // 625

// ---------------- device scratch ----------------
__device__ __half g_node[(size_t)N_NODES * H];
__device__ __half g_P[(size_t)N_NODES * H];
__device__ __half g_h0[(size_t)N_EDGES * H];
__device__ __half g_hA[(size_t)N_EDGES * H];
__device__ __half g_hB[(size_t)N_EDGES * H];
__device__ __half g_aggA[(size_t)N_NODES * H];   // fp16 segment sums (f16x2 atomics)
__device__ __half g_aggB[(size_t)N_NODES * H];
__device__ float g_gpool[(size_t)N_GRAPHS * H];
__device__ float g_Wc[EDGE_DIM * H];
__device__ float g_bc[H];

__device__ __forceinline__ float lrelu(float v) { return fmaxf(v, 0.01f * v); }

__device__ __forceinline__ void red_h2(__half* p, float x, float y) {
    __half2 hv = __floats2half2_rn(x, y);
    asm volatile("red.global.add.noftz.f16x2 [%0], %1;"
                 :: "l"(p), "r"(*(unsigned*)&hv) : "memory");
}

#define LDMX4(r0, r1, r2, r3, gaddr)                                          \
    asm volatile("ldmatrix.sync.aligned.m8n8.x4.shared.b16 {%0,%1,%2,%3}, [%4];" \
                 : "=r"(r0), "=r"(r1), "=r"(r2), "=r"(r3) : "r"(gaddr))
#define LDMX4T(r0, r1, r2, r3, gaddr)                                         \
    asm volatile("ldmatrix.sync.aligned.m8n8.x4.trans.shared.b16 {%0,%1,%2,%3}, [%4];" \
                 : "=r"(r0), "=r"(r1), "=r"(r2), "=r"(r3) : "r"(gaddr))
#define MMA16816(acc, a0, a1, a2, a3, b0, b1)                                 \
    asm volatile("mma.sync.aligned.m16n8k16.row.col.f32.f16.f16.f32 "         \
                 "{%0,%1,%2,%3}, {%4,%5,%6,%7}, {%8,%9}, {%0,%1,%2,%3};"      \
                 : "+f"(acc[0]), "+f"(acc[1]), "+f"(acc[2]), "+f"(acc[3])     \
                 : "r"(a0), "r"(a1), "r"(a2), "r"(a3), "r"(b0), "r"(b1))

// ---------------- prep: fold edge projection through Wi ----------------
__global__ void prep_kernel(const float* __restrict__ We, const float* __restrict__ be,
                            const float* __restrict__ Wi, const float* __restrict__ bi,
                            float* __restrict__ Wc, float* __restrict__ bc) {
    int tid = blockIdx.x * blockDim.x + threadIdx.x;
    if (tid < EDGE_DIM * H) {
        int d = tid >> 6, j = tid & 63;
        float s = 0.f;
        #pragma unroll 8
        for (int k = 0; k < H; k++) s += We[d * H + k] * Wi[(H + k) * H + j];
        Wc[tid] = s;
    }
    if (tid < H) {
        float s = bi[tid];
        #pragma unroll 8
        for (int k = 0; k < H; k++) s += be[k] * Wi[(H + k) * H + tid];
        bc[tid] = s;
    }
}

// ---------------- node projection via HMMA (K=74 padded to 80) ----------------
#define LDA 88
__global__ __launch_bounds__(256) void node_proj_mma_kernel(
    const float* __restrict__ nf, const float* __restrict__ Wn,
    const float* __restrict__ bn, __half* __restrict__ node) {
    __shared__ __align__(16) __half sW[80 * 72];
    __shared__ __align__(16) __half sT[8][16 * LDA];
    __shared__ float sb[64];

    int tid = threadIdx.x;
    for (int idx = tid; idx < 80 * 64; idx += 256) {
        int k = idx >> 6, n = idx & 63;
        sW[k * 72 + n] = (k < NODE_DIM) ? __float2half_rn(Wn[k * H + n]) : __half(0.f);
    }
    if (tid < 64) sb[tid] = bn[tid];
    __syncthreads();
    int warp = tid >> 5, lane = tid & 31;

    unsigned bfr[8][5][2];
    #pragma unroll
    for (int nt = 0; nt < 8; nt++) {
        #pragma unroll
        for (int kh = 0; kh < 2; kh++) {
            unsigned r0, r1, r2, r3;
            unsigned addr = (unsigned)__cvta_generic_to_shared(&sW[(kh * 32 + lane) * 72 + nt * 8]);
            LDMX4T(r0, r1, r2, r3, addr);
            bfr[nt][kh * 2][0] = r0;     bfr[nt][kh * 2][1] = r1;
            bfr[nt][kh * 2 + 1][0] = r2; bfr[nt][kh * 2 + 1][1] = r3;
        }
        unsigned r0, r1;
        unsigned addr = (unsigned)__cvta_generic_to_shared(&sW[(64 + (lane & 15)) * 72 + nt * 8]);
        asm volatile("ldmatrix.sync.aligned.m8n8.x2.trans.shared.b16 {%0,%1}, [%2];"
                     : "=r"(r0), "=r"(r1) : "r"(addr));
        bfr[nt][4][0] = r0; bfr[nt][4][1] = r1;
    }

    __half* myT = sT[warp];
    for (int idx = lane; idx < 16 * 3; idx += 32) {
        int r = idx / 3, c = 74 + (idx % 3) * 2;
        *(__half2*)&myT[r * LDA + c] = __floats2half2_rn(0.f, 0.f);
    }
    __syncwarp();

    int base = ((blockIdx.x * 8 + warp) * CT) * 16;
    int am = lane >> 3;
    int arow = (am & 1) * 8 + (lane & 7);
    int acol0 = (am >> 1) * 8;

    for (int t = 0; t < CT; t++) {
        int nb = base + t * 16;
        #pragma unroll
        for (int i = 0; i < 16; i++) {
            const float* row = nf + (size_t)(nb + i) * NODE_DIM;
            float2 f = *(const float2*)&row[2 * lane];
            *(__half2*)&myT[i * LDA + 2 * lane] = __floats2half2_rn(f.x, f.y);
            if (lane < 5) {
                float2 g = *(const float2*)&row[64 + 2 * lane];
                *(__half2*)&myT[i * LDA + 64 + 2 * lane] = __floats2half2_rn(g.x, g.y);
            }
        }
        __syncwarp();
        float acc[8][4];
        #pragma unroll
        for (int nt = 0; nt < 8; nt++) { acc[nt][0]=0.f; acc[nt][1]=0.f; acc[nt][2]=0.f; acc[nt][3]=0.f; }
        #pragma unroll
        for (int kt = 0; kt < 5; kt++) {
            unsigned a0, a1, a2, a3;
            unsigned addr = (unsigned)__cvta_generic_to_shared(&myT[arow * LDA + kt * 16 + acol0]);
            LDMX4(a0, a1, a2, a3, addr);
            #pragma unroll
            for (int nt = 0; nt < 8; nt++)
                MMA16816(acc[nt], a0, a1, a2, a3, bfr[nt][kt][0], bfr[nt][kt][1]);
        }
        __syncwarp();
        int qrow = lane >> 2, qc = (lane & 3) * 2;
        #pragma unroll
        for (int nt = 0; nt < 8; nt++) {
            float b0 = sb[nt * 8 + qc], b1 = sb[nt * 8 + qc + 1];
            *(__half2*)&myT[qrow * LDA + nt * 8 + qc]       = __floats2half2_rn(acc[nt][0] + b0, acc[nt][1] + b1);
            *(__half2*)&myT[(qrow + 8) * LDA + nt * 8 + qc] = __floats2half2_rn(acc[nt][2] + b0, acc[nt][3] + b1);
        }
        __syncwarp();
        #pragma unroll
        for (int i = 0; i < 16; i++)
            *(__half2*)&node[(nb + i) * 64 + 2 * lane] = *(__half2*)&myT[i * LDA + 2 * lane];
        __syncwarp();
    }
}

// ---------------- P = node @ Wi_top (dense fp16 MMA GEMM) ----------------
__global__ __launch_bounds__(256) void pmma_kernel(
    const __half* __restrict__ node, const float* __restrict__ Wi,
    __half* __restrict__ P) {
    __shared__ __align__(16) __half sW[64 * 72];
    __shared__ __align__(16) __half sT[8][16 * 72];
    int tid = threadIdx.x;
    for (int idx = tid; idx < 64 * 64; idx += 256) {
        int k = idx >> 6, n = idx & 63;
        sW[k * 72 + n] = __float2half_rn(Wi[k * H + n]);
    }
    __syncthreads();
    int warp = tid >> 5, lane = tid & 31;

    unsigned bfr[8][4][2];
    #pragma unroll
    for (int nt = 0; nt < 8; nt++) {
        #pragma unroll
        for (int kh = 0; kh < 2; kh++) {
            unsigned r0, r1, r2, r3;
            unsigned addr = (unsigned)__cvta_generic_to_shared(&sW[(kh * 32 + lane) * 72 + nt * 8]);
            LDMX4T(r0, r1, r2, r3, addr);
            bfr[nt][kh * 2][0] = r0;     bfr[nt][kh * 2][1] = r1;
            bfr[nt][kh * 2 + 1][0] = r2; bfr[nt][kh * 2 + 1][1] = r3;
        }
    }
    __half* myT = sT[warp];
    int base = ((blockIdx.x * 8 + warp) * CT) * 16;
    int am = lane >> 3;
    int arow = (am & 1) * 8 + (lane & 7);
    int acol0 = (am >> 1) * 8;

    for (int t = 0; t < CT; t++) {
        int nb = base + t * 16;
        #pragma unroll
        for (int i = 0; i < 16; i++)
            *(__half2*)&myT[i * 72 + 2 * lane] = *(const __half2*)&node[(nb + i) * 64 + 2 * lane];
        __syncwarp();
        float acc[8][4];
        #pragma unroll
        for (int nt = 0; nt < 8; nt++) { acc[nt][0]=0.f; acc[nt][1]=0.f; acc[nt][2]=0.f; acc[nt][3]=0.f; }
        #pragma unroll
        for (int kt = 0; kt < 4; kt++) {
            unsigned a0, a1, a2, a3;
            unsigned addr = (unsigned)__cvta_generic_to_shared(&myT[arow * 72 + kt * 16 + acol0]);
            LDMX4(a0, a1, a2, a3, addr);
            #pragma unroll
            for (int nt = 0; nt < 8; nt++)
                MMA16816(acc[nt], a0, a1, a2, a3, bfr[nt][kt][0], bfr[nt][kt][1]);
        }
        __syncwarp();
        int qrow = lane >> 2, qc = (lane & 3) * 2;
        #pragma unroll
        for (int nt = 0; nt < 8; nt++) {
            *(__half2*)&myT[qrow * 72 + nt * 8 + qc]       = __floats2half2_rn(acc[nt][0], acc[nt][1]);
            *(__half2*)&myT[(qrow + 8) * 72 + nt * 8 + qc] = __floats2half2_rn(acc[nt][2], acc[nt][3]);
        }
        __syncwarp();
        #pragma unroll
        for (int i = 0; i < 16; i++)
            *(__half2*)&P[(nb + i) * 64 + 2 * lane] = *(__half2*)&myT[i * 72 + 2 * lane];
        __syncwarp();
    }
}

// ---------------- h0_lite: h0 = lrelu(P[src] + ef@Wc + bc), scatter fp16 agg ----------------
// wc kept as __half2 (13 regs instead of 26) -> natural fit in the 64-reg tier
__global__ __launch_bounds__(256) void h0_lite_kernel(
    const __half* __restrict__ P, const float* __restrict__ ef,
    const int* __restrict__ src, const int* __restrict__ dst,
    const float* __restrict__ Wc, const float* __restrict__ bc,
    __half* __restrict__ h0, __half* __restrict__ agg_out) {
    __shared__ float sEf[WPB][16 * EDGE_DIM];
    int tid = threadIdx.x, warp = tid >> 5, lane = tid & 31;
    int eb = (blockIdx.x * WPB + warp) * 16;

    __half2 wc[EDGE_DIM];
    #pragma unroll
    for (int d = 0; d < EDGE_DIM; d++) {
        float2 w = *(const float2*)&Wc[d * H + 2 * lane];
        wc[d] = __floats2half2_rn(w.x, w.y);
    }
    float2 bc2 = *(const float2*)&bc[2 * lane];

    float* myEf = sEf[warp];
    for (int idx = lane; idx < 16 * EDGE_DIM; idx += 32)
        myEf[idx] = ef[(size_t)eb * EDGE_DIM + idx];
    int sidx = src[eb + (lane & 15)];
    int didx = dst[eb + (lane & 15)];
    __syncwarp();

    #pragma unroll
    for (int i = 0; i < 16; i++) {
        int s = __shfl_sync(0xffffffffu, sidx, i);
        int d = __shfl_sync(0xffffffffu, didx, i);
        float2 p2 = __half22float2(*(const __half2*)&P[s * 64 + 2 * lane]);
        float a0 = p2.x + bc2.x, a1 = p2.y + bc2.y;
        #pragma unroll
        for (int k = 0; k < EDGE_DIM; k++) {
            float e = myEf[i * EDGE_DIM + k];
            float2 w = __half22float2(wc[k]);
            a0 += e * w.x; a1 += e * w.y;
        }
        float o0 = lrelu(a0), o1 = lrelu(a1);
        *(__half2*)&h0[(size_t)(eb + i) * 64 + 2 * lane] = __floats2half2_rn(o0, o1);
        red_h2(&agg_out[d * 64 + 2 * lane], o0, o1);
    }
}

// ---------------- conv layer: HMMA, fp16 agg gather + scatter (R14 verbatim) ----------------
__global__ __launch_bounds__(256, 3) void conv_mma_kernel(
    const float* __restrict__ W, const float* __restrict__ bias,
    const int* __restrict__ src, const int* __restrict__ dst,
    const __half* __restrict__ agg_in, const __half* __restrict__ h_in,
    const __half* __restrict__ h0, __half* __restrict__ h_out,
    __half* __restrict__ agg_out) {
    __shared__ __align__(16) __half sW[64 * 72];
    __shared__ __align__(16) __half sT[8][16 * 72];

    int tid = threadIdx.x;
    for (int idx = tid; idx < 64 * 64; idx += 256) {
        int k = idx >> 6, n = idx & 63;
        sW[k * 72 + n] = __float2half_rn(W[idx]);
    }
    __syncthreads();
    int warp = tid >> 5, lane = tid & 31;
    float2 bias2 = *(const float2*)&bias[2 * lane];

    __half* myT = sT[warp];
    int base = ((blockIdx.x * 8 + warp) * CT) * 16;
    int am = lane >> 3;
    int arow = (am & 1) * 8 + (lane & 7);
    int acol0 = (am >> 1) * 8;

    for (int t = 0; t < CT; t++) {
        int eb = base + t * 16;
        int sidx = src[eb + (lane & 15)];
        int didx = dst[eb + (lane & 15)];
        #pragma unroll
        for (int i = 0; i < 16; i++) {
            int s = __shfl_sync(0xffffffffu, sidx, i);
            int r = (eb + i) ^ 1;
            float2 a = __half22float2(*(const __half2*)&agg_in[s * 64 + 2 * lane]);
            float2 hf = __half22float2(*(const __half2*)&h_in[r * 64 + 2 * lane]);
            *(__half2*)&myT[i * 72 + 2 * lane] = __floats2half2_rn(a.x - hf.x, a.y - hf.y);
        }
        __syncwarp();
        float acc[8][4];
        #pragma unroll
        for (int nt = 0; nt < 8; nt++) { acc[nt][0]=0.f; acc[nt][1]=0.f; acc[nt][2]=0.f; acc[nt][3]=0.f; }
        #pragma unroll
        for (int kh = 0; kh < 2; kh++) {
            unsigned a00, a01, a02, a03, a10, a11, a12, a13;
            unsigned addr0 = (unsigned)__cvta_generic_to_shared(&myT[arow * 72 + (2 * kh) * 16 + acol0]);
            LDMX4(a00, a01, a02, a03, addr0);
            unsigned addr1 = (unsigned)__cvta_generic_to_shared(&myT[arow * 72 + (2 * kh + 1) * 16 + acol0]);
            LDMX4(a10, a11, a12, a13, addr1);
            #pragma unroll
            for (int nt = 0; nt < 8; nt++) {
                unsigned b0, b1, b2, b3;
                unsigned addrB = (unsigned)__cvta_generic_to_shared(&sW[(kh * 32 + lane) * 72 + nt * 8]);
                LDMX4T(b0, b1, b2, b3, addrB);
                MMA16816(acc[nt], a00, a01, a02, a03, b0, b1);
                MMA16816(acc[nt], a10, a11, a12, a13, b2, b3);
            }
        }
        __syncwarp();
        int qrow = lane >> 2, qc = (lane & 3) * 2;
        #pragma unroll
        for (int nt = 0; nt < 8; nt++) {
            *(__half2*)&myT[qrow * 72 + nt * 8 + qc]       = __floats2half2_rn(acc[nt][0], acc[nt][1]);
            *(__half2*)&myT[(qrow + 8) * 72 + nt * 8 + qc] = __floats2half2_rn(acc[nt][2], acc[nt][3]);
        }
        __syncwarp();
        #pragma unroll
        for (int i = 0; i < 16; i++) {
            int d = __shfl_sync(0xffffffffu, didx, i);
            float2 m2  = __half22float2(*(const __half2*)&myT[i * 72 + 2 * lane]);
            float2 h0f = __half22float2(*(const __half2*)&h0[(eb + i) * 64 + 2 * lane]);
            float o0 = lrelu(h0f.x + bias2.x + m2.x);
            float o1 = lrelu(h0f.y + bias2.y + m2.y);
            *(__half2*)&h_out[(eb + i) * 64 + 2 * lane] = __floats2half2_rn(o0, o1);
            red_h2(&agg_out[d * 64 + 2 * lane], o0, o1);
        }
        __syncwarp();
    }
}

// ---------------- readout via HMMA: gpool[gid[n]] += lrelu([node,agg]@Wa + ba) ----------------
__global__ __launch_bounds__(256, 3) void readout_mma_kernel(
    const __half* __restrict__ node, const __half* __restrict__ agg,
    const float* __restrict__ Wa, const float* __restrict__ ba,
    const int* __restrict__ gid, float* __restrict__ gpool) {
    __shared__ __align__(16) __half sW[128 * 72];
    __shared__ __align__(16) __half sT[8][16 * 72];
    __shared__ float sba[64];

    int tid = threadIdx.x;
    for (int idx = tid; idx < 128 * 64; idx += 256) {
        int k = idx >> 6, n = idx & 63;
        sW[k * 72 + n] = __float2half_rn(Wa[k * H + n]);
    }
    if (tid < 64) sba[tid] = ba[tid];
    __syncthreads();
    int warp = tid >> 5, lane = tid & 31;

    __half* myT = sT[warp];
    int base = ((blockIdx.x * 8 + warp) * CT) * 16;
    int am = lane >> 3;
    int arow = (am & 1) * 8 + (lane & 7);
    int acol0 = (am >> 1) * 8;

    for (int t = 0; t < CT; t++) {
        int nb = base + t * 16;
        int gidx = gid[nb + (lane & 15)];
        float acc[8][4];
        #pragma unroll
        for (int nt = 0; nt < 8; nt++) { acc[nt][0]=0.f; acc[nt][1]=0.f; acc[nt][2]=0.f; acc[nt][3]=0.f; }

        #pragma unroll
        for (int stage = 0; stage < 2; stage++) {
            #pragma unroll
            for (int i = 0; i < 16; i++) {
                const __half* in = stage ? &agg[(nb + i) * 64] : &node[(nb + i) * 64];
                *(__half2*)&myT[i * 72 + 2 * lane] = *(const __half2*)&in[2 * lane];
            }
            __syncwarp();
            #pragma unroll
            for (int kh = 0; kh < 2; kh++) {
                unsigned a00, a01, a02, a03, a10, a11, a12, a13;
                unsigned addr0 = (unsigned)__cvta_generic_to_shared(&myT[arow * 72 + (2 * kh) * 16 + acol0]);
                LDMX4(a00, a01, a02, a03, addr0);
                unsigned addr1 = (unsigned)__cvta_generic_to_shared(&myT[arow * 72 + (2 * kh + 1) * 16 + acol0]);
                LDMX4(a10, a11, a12, a13, addr1);
                #pragma unroll
                for (int nt = 0; nt < 8; nt++) {
                    unsigned b0, b1, b2, b3;
                    unsigned addrB = (unsigned)__cvta_generic_to_shared(
                        &sW[(stage * 64 + kh * 32 + lane) * 72 + nt * 8]);
                    LDMX4T(b0, b1, b2, b3, addrB);
                    MMA16816(acc[nt], a00, a01, a02, a03, b0, b1);
                    MMA16816(acc[nt], a10, a11, a12, a13, b2, b3);
                }
            }
            __syncwarp();
        }
        int qrow = lane >> 2, qc = (lane & 3) * 2;
        int g0 = __shfl_sync(0xffffffffu, gidx, qrow);
        int g1 = __shfl_sync(0xffffffffu, gidx, qrow + 8);
        #pragma unroll
        for (int nt = 0; nt < 8; nt++) {
            float b0 = sba[nt * 8 + qc], b1 = sba[nt * 8 + qc + 1];
            float o00 = lrelu(acc[nt][0] + b0), o01 = lrelu(acc[nt][1] + b1);
            float o10 = lrelu(acc[nt][2] + b0), o11 = lrelu(acc[nt][3] + b1);
            asm volatile("red.global.add.v2.f32 [%0], {%1, %2};"
                         :: "l"(&gpool[g0 * 64 + nt * 8 + qc]), "f"(o00), "f"(o01) : "memory");
            asm volatile("red.global.add.v2.f32 [%0], {%1, %2};"
                         :: "l"(&gpool[g1 * 64 + nt * 8 + qc]), "f"(o10), "f"(o11) : "memory");
        }
    }
}

// ---------------- head ----------------
__global__ __launch_bounds__(256) void head_kernel(
    const float* __restrict__ g, const float* __restrict__ W1,
    const float* __restrict__ b1, const float* __restrict__ W2,
    const float* __restrict__ b2, float* __restrict__ out) {
    __shared__ float2 sW[H * 32];
    __shared__ float sb[H];
    __shared__ float sW2[H];
    for (int idx = threadIdx.x; idx < H * 32; idx += 256) {
        int k = idx >> 5, j = idx & 31;
        sW[idx] = make_float2(W1[k * H + j], W1[k * H + j + 32]);
    }
    if (threadIdx.x < H) { sb[threadIdx.x] = b1[threadIdx.x]; sW2[threadIdx.x] = W2[threadIdx.x]; }
    __syncthreads();
    int warp = threadIdx.x >> 5, lane = threadIdx.x & 31;
    int gi = blockIdx.x * 8 + warp;
    const float* row = g + gi * H;
    float f0 = row[lane], f1 = row[lane + 32];
    float a0 = sb[lane], a1 = sb[lane + 32];
    #pragma unroll
    for (int k = 0; k < H; k++) {
        float fk = __shfl_sync(0xffffffffu, (k < 32 ? f0 : f1), k & 31);
        float2 w = sW[k * 32 + lane];
        a0 += fk * w.x; a1 += fk * w.y;
    }
    a0 = lrelu(a0); a1 = lrelu(a1);
    float p = a0 * sW2[lane] + a1 * sW2[lane + 32];
    #pragma unroll
    for (int o = 16; o; o >>= 1) p += __shfl_xor_sync(0xffffffffu, p, o);
    if (lane == 0) out[gi] = p + b2[0];
}

// ---------------- launch ----------------
extern "C" void kernel_launch(void* const* d_in, const int* in_sizes, int n_in,
                              void* d_out, int out_size) {
    const float* node_feats = (const float*)d_in[0];
    const float* edge_feats = (const float*)d_in[1];
    const int*   src        = (const int*)d_in[2];
    const int*   dst        = (const int*)d_in[3];
    const int*   gid        = (const int*)d_in[4];
    const float* Wn = (const float*)d_in[5];
    const float* bn = (const float*)d_in[6];
    const float* We = (const float*)d_in[7];
    const float* be = (const float*)d_in[8];
    const float* Wi = (const float*)d_in[9];
    const float* bi = (const float*)d_in[10];
    const float* Wa = (const float*)d_in[11];
    const float* ba = (const float*)d_in[12];
    const float* Wl = (const float*)d_in[13];
    const float* bl = (const float*)d_in[14];
    const float* W1 = (const float*)d_in[15];
    const float* b1 = (const float*)d_in[16];
    const float* W2 = (const float*)d_in[17];
    const float* b2 = (const float*)d_in[18];
    float* out = (float*)d_out;

    __half *p_node, *p_P, *p_h0, *p_hA, *p_hB, *p_aggA, *p_aggB;
    float *p_gpool, *p_Wc, *p_bc;
    cudaGetSymbolAddress((void**)&p_node, g_node);
    cudaGetSymbolAddress((void**)&p_P, g_P);
    cudaGetSymbolAddress((void**)&p_h0, g_h0);
    cudaGetSymbolAddress((void**)&p_hA, g_hA);
    cudaGetSymbolAddress((void**)&p_hB, g_hB);
    cudaGetSymbolAddress((void**)&p_aggA, g_aggA);
    cudaGetSymbolAddress((void**)&p_aggB, g_aggB);
    cudaGetSymbolAddress((void**)&p_gpool, g_gpool);
    cudaGetSymbolAddress((void**)&p_Wc, g_Wc);
    cudaGetSymbolAddress((void**)&p_bc, g_bc);

    const size_t aggBytes = (size_t)N_NODES * H * sizeof(__half);

    prep_kernel<<<4, 256>>>(We, be, Wi, bi, p_Wc, p_bc);
    node_proj_mma_kernel<<<PGRID, 256>>>(node_feats, Wn, bn, p_node);
    pmma_kernel<<<PGRID, 256>>>(p_node, Wi, p_P);

    cudaMemsetAsync(p_aggA, 0, aggBytes);
    h0_lite_kernel<<<H0GRID, 256>>>(p_P, edge_feats, src, dst, p_Wc, p_bc,
                                    p_h0, p_aggA);

    cudaMemsetAsync(p_aggB, 0, aggBytes);
    conv_mma_kernel<<<CGRID, 256>>>(Wl + 0 * H * H, bl + 0 * H, src, dst,
                                    p_aggA, p_h0, p_h0, p_hA, p_aggB);
    cudaMemsetAsync(p_aggA, 0, aggBytes);
    conv_mma_kernel<<<CGRID, 256>>>(Wl + 1 * H * H, bl + 1 * H, src, dst,
                                    p_aggB, p_hA, p_h0, p_hB, p_aggA);
    cudaMemsetAsync(p_aggB, 0, aggBytes);
    conv_mma_kernel<<<CGRID, 256>>>(Wl + 2 * H * H, bl + 2 * H, src, dst,
                                    p_aggA, p_hB, p_h0, p_hA, p_aggB);
    cudaMemsetAsync(p_aggA, 0, aggBytes);
    conv_mma_kernel<<<CGRID, 256>>>(Wl + 3 * H * H, bl + 3 * H, src, dst,
                                    p_aggB, p_hA, p_h0, p_hB, p_aggA);

    cudaMemsetAsync(p_gpool, 0, (size_t)N_GRAPHS * H * sizeof(float));
    readout_mma_kernel<<<PGRID, 256>>>(p_node, p_aggA, Wa, ba, gid, p_gpool);
    head_kernel<<<N_GRAPHS / 8, 256>>>(p_gpool, W1, b1, W2, b2, out);
}

// round 17
// speedup vs baseline: 1.2317x; 1.0243x over previous
#include <cuda_runtime.h>
#include <cuda_fp16.h>

#define N_NODES 400000
#define N_EDGES 1600000
#define N_GRAPHS 10000
#define H 64
#define NODE_DIM 74
#define EDGE_DIM 13
#define WPB 8
#define CT 5         // 16-row tiles per warp in MMA kernels

#define CGRID  (N_EDGES / (WPB * CT * 16))   // 2500
#define H0GRID (N_EDGES / (WPB * 8))         // 25000 (8 edges per warp)
#define PGRID  (N_NODES / (WPB * CT * 16))   // 625

// ---------------- device scratch ----------------
__device__ __half g_node[(size_t)N_NODES * H];
__device__ __half g_P[(size_t)N_NODES * H];
__device__ __half g_h0[(size_t)N_EDGES * H];
__device__ __half g_hA[(size_t)N_EDGES * H];
__device__ __half g_hB[(size_t)N_EDGES * H];
__device__ __half g_aggA[(size_t)N_NODES * H];   // fp16 segment sums (f16x2 atomics)
__device__ __half g_aggB[(size_t)N_NODES * H];
__device__ float g_gpool[(size_t)N_GRAPHS * H];
__device__ float g_Wc[EDGE_DIM * H];
__device__ float g_bc[H];

__device__ __forceinline__ float lrelu(float v) { return fmaxf(v, 0.01f * v); }

__device__ __forceinline__ void red_h2(__half* p, float x, float y) {
    __half2 hv = __floats2half2_rn(x, y);
    asm volatile("red.global.add.noftz.f16x2 [%0], %1;"
                 :: "l"(p), "r"(*(unsigned*)&hv) : "memory");
}

#define LDMX4(r0, r1, r2, r3, gaddr)                                          \
    asm volatile("ldmatrix.sync.aligned.m8n8.x4.shared.b16 {%0,%1,%2,%3}, [%4];" \
                 : "=r"(r0), "=r"(r1), "=r"(r2), "=r"(r3) : "r"(gaddr))
#define LDMX4T(r0, r1, r2, r3, gaddr)                                         \
    asm volatile("ldmatrix.sync.aligned.m8n8.x4.trans.shared.b16 {%0,%1,%2,%3}, [%4];" \
                 : "=r"(r0), "=r"(r1), "=r"(r2), "=r"(r3) : "r"(gaddr))
#define MMA16816(acc, a0, a1, a2, a3, b0, b1)                                 \
    asm volatile("mma.sync.aligned.m16n8k16.row.col.f32.f16.f16.f32 "         \
                 "{%0,%1,%2,%3}, {%4,%5,%6,%7}, {%8,%9}, {%0,%1,%2,%3};"      \
                 : "+f"(acc[0]), "+f"(acc[1]), "+f"(acc[2]), "+f"(acc[3])     \
                 : "r"(a0), "r"(a1), "r"(a2), "r"(a3), "r"(b0), "r"(b1))

// ---------------- prep: fold edge projection through Wi ----------------
__global__ void prep_kernel(const float* __restrict__ We, const float* __restrict__ be,
                            const float* __restrict__ Wi, const float* __restrict__ bi,
                            float* __restrict__ Wc, float* __restrict__ bc) {
    int tid = blockIdx.x * blockDim.x + threadIdx.x;
    if (tid < EDGE_DIM * H) {
        int d = tid >> 6, j = tid & 63;
        float s = 0.f;
        #pragma unroll 8
        for (int k = 0; k < H; k++) s += We[d * H + k] * Wi[(H + k) * H + j];
        Wc[tid] = s;
    }
    if (tid < H) {
        float s = bi[tid];
        #pragma unroll 8
        for (int k = 0; k < H; k++) s += be[k] * Wi[(H + k) * H + tid];
        bc[tid] = s;
    }
}

// ---------------- node projection via HMMA (K=74 padded to 80) ----------------
#define LDA 88
__global__ __launch_bounds__(256) void node_proj_mma_kernel(
    const float* __restrict__ nf, const float* __restrict__ Wn,
    const float* __restrict__ bn, __half* __restrict__ node) {
    __shared__ __align__(16) __half sW[80 * 72];
    __shared__ __align__(16) __half sT[8][16 * LDA];
    __shared__ float sb[64];

    int tid = threadIdx.x;
    for (int idx = tid; idx < 80 * 64; idx += 256) {
        int k = idx >> 6, n = idx & 63;
        sW[k * 72 + n] = (k < NODE_DIM) ? __float2half_rn(Wn[k * H + n]) : __half(0.f);
    }
    if (tid < 64) sb[tid] = bn[tid];
    __syncthreads();
    int warp = tid >> 5, lane = tid & 31;

    unsigned bfr[8][5][2];
    #pragma unroll
    for (int nt = 0; nt < 8; nt++) {
        #pragma unroll
        for (int kh = 0; kh < 2; kh++) {
            unsigned r0, r1, r2, r3;
            unsigned addr = (unsigned)__cvta_generic_to_shared(&sW[(kh * 32 + lane) * 72 + nt * 8]);
            LDMX4T(r0, r1, r2, r3, addr);
            bfr[nt][kh * 2][0] = r0;     bfr[nt][kh * 2][1] = r1;
            bfr[nt][kh * 2 + 1][0] = r2; bfr[nt][kh * 2 + 1][1] = r3;
        }
        unsigned r0, r1;
        unsigned addr = (unsigned)__cvta_generic_to_shared(&sW[(64 + (lane & 15)) * 72 + nt * 8]);
        asm volatile("ldmatrix.sync.aligned.m8n8.x2.trans.shared.b16 {%0,%1}, [%2];"
                     : "=r"(r0), "=r"(r1) : "r"(addr));
        bfr[nt][4][0] = r0; bfr[nt][4][1] = r1;
    }

    __half* myT = sT[warp];
    for (int idx = lane; idx < 16 * 3; idx += 32) {
        int r = idx / 3, c = 74 + (idx % 3) * 2;
        *(__half2*)&myT[r * LDA + c] = __floats2half2_rn(0.f, 0.f);
    }
    __syncwarp();

    int base = ((blockIdx.x * 8 + warp) * CT) * 16;
    int am = lane >> 3;
    int arow = (am & 1) * 8 + (lane & 7);
    int acol0 = (am >> 1) * 8;

    for (int t = 0; t < CT; t++) {
        int nb = base + t * 16;
        #pragma unroll
        for (int i = 0; i < 16; i++) {
            const float* row = nf + (size_t)(nb + i) * NODE_DIM;
            float2 f = *(const float2*)&row[2 * lane];
            *(__half2*)&myT[i * LDA + 2 * lane] = __floats2half2_rn(f.x, f.y);
            if (lane < 5) {
                float2 g = *(const float2*)&row[64 + 2 * lane];
                *(__half2*)&myT[i * LDA + 64 + 2 * lane] = __floats2half2_rn(g.x, g.y);
            }
        }
        __syncwarp();
        float acc[8][4];
        #pragma unroll
        for (int nt = 0; nt < 8; nt++) { acc[nt][0]=0.f; acc[nt][1]=0.f; acc[nt][2]=0.f; acc[nt][3]=0.f; }
        #pragma unroll
        for (int kt = 0; kt < 5; kt++) {
            unsigned a0, a1, a2, a3;
            unsigned addr = (unsigned)__cvta_generic_to_shared(&myT[arow * LDA + kt * 16 + acol0]);
            LDMX4(a0, a1, a2, a3, addr);
            #pragma unroll
            for (int nt = 0; nt < 8; nt++)
                MMA16816(acc[nt], a0, a1, a2, a3, bfr[nt][kt][0], bfr[nt][kt][1]);
        }
        __syncwarp();
        int qrow = lane >> 2, qc = (lane & 3) * 2;
        #pragma unroll
        for (int nt = 0; nt < 8; nt++) {
            float b0 = sb[nt * 8 + qc], b1 = sb[nt * 8 + qc + 1];
            *(__half2*)&myT[qrow * LDA + nt * 8 + qc]       = __floats2half2_rn(acc[nt][0] + b0, acc[nt][1] + b1);
            *(__half2*)&myT[(qrow + 8) * LDA + nt * 8 + qc] = __floats2half2_rn(acc[nt][2] + b0, acc[nt][3] + b1);
        }
        __syncwarp();
        #pragma unroll
        for (int i = 0; i < 16; i++)
            *(__half2*)&node[(nb + i) * 64 + 2 * lane] = *(__half2*)&myT[i * LDA + 2 * lane];
        __syncwarp();
    }
}

// ---------------- P = node @ Wi_top (dense fp16 MMA GEMM) ----------------
__global__ __launch_bounds__(256) void pmma_kernel(
    const __half* __restrict__ node, const float* __restrict__ Wi,
    __half* __restrict__ P) {
    __shared__ __align__(16) __half sW[64 * 72];
    __shared__ __align__(16) __half sT[8][16 * 72];
    int tid = threadIdx.x;
    for (int idx = tid; idx < 64 * 64; idx += 256) {
        int k = idx >> 6, n = idx & 63;
        sW[k * 72 + n] = __float2half_rn(Wi[k * H + n]);
    }
    __syncthreads();
    int warp = tid >> 5, lane = tid & 31;

    unsigned bfr[8][4][2];
    #pragma unroll
    for (int nt = 0; nt < 8; nt++) {
        #pragma unroll
        for (int kh = 0; kh < 2; kh++) {
            unsigned r0, r1, r2, r3;
            unsigned addr = (unsigned)__cvta_generic_to_shared(&sW[(kh * 32 + lane) * 72 + nt * 8]);
            LDMX4T(r0, r1, r2, r3, addr);
            bfr[nt][kh * 2][0] = r0;     bfr[nt][kh * 2][1] = r1;
            bfr[nt][kh * 2 + 1][0] = r2; bfr[nt][kh * 2 + 1][1] = r3;
        }
    }
    __half* myT = sT[warp];
    int base = ((blockIdx.x * 8 + warp) * CT) * 16;
    int am = lane >> 3;
    int arow = (am & 1) * 8 + (lane & 7);
    int acol0 = (am >> 1) * 8;

    for (int t = 0; t < CT; t++) {
        int nb = base + t * 16;
        #pragma unroll
        for (int i = 0; i < 16; i++)
            *(__half2*)&myT[i * 72 + 2 * lane] = *(const __half2*)&node[(nb + i) * 64 + 2 * lane];
        __syncwarp();
        float acc[8][4];
        #pragma unroll
        for (int nt = 0; nt < 8; nt++) { acc[nt][0]=0.f; acc[nt][1]=0.f; acc[nt][2]=0.f; acc[nt][3]=0.f; }
        #pragma unroll
        for (int kt = 0; kt < 4; kt++) {
            unsigned a0, a1, a2, a3;
            unsigned addr = (unsigned)__cvta_generic_to_shared(&myT[arow * 72 + kt * 16 + acol0]);
            LDMX4(a0, a1, a2, a3, addr);
            #pragma unroll
            for (int nt = 0; nt < 8; nt++)
                MMA16816(acc[nt], a0, a1, a2, a3, bfr[nt][kt][0], bfr[nt][kt][1]);
        }
        __syncwarp();
        int qrow = lane >> 2, qc = (lane & 3) * 2;
        #pragma unroll
        for (int nt = 0; nt < 8; nt++) {
            *(__half2*)&myT[qrow * 72 + nt * 8 + qc]       = __floats2half2_rn(acc[nt][0], acc[nt][1]);
            *(__half2*)&myT[(qrow + 8) * 72 + nt * 8 + qc] = __floats2half2_rn(acc[nt][2], acc[nt][3]);
        }
        __syncwarp();
        #pragma unroll
        for (int i = 0; i < 16; i++)
            *(__half2*)&P[(nb + i) * 64 + 2 * lane] = *(__half2*)&myT[i * 72 + 2 * lane];
        __syncwarp();
    }
}

// ---------------- h0_lite: 8 edges/warp (lower regs -> 4 blocks/SM) ----------------
__global__ __launch_bounds__(256) void h0_lite_kernel(
    const __half* __restrict__ P, const float* __restrict__ ef,
    const int* __restrict__ src, const int* __restrict__ dst,
    const float* __restrict__ Wc, const float* __restrict__ bc,
    __half* __restrict__ h0, __half* __restrict__ agg_out) {
    __shared__ float sEf[WPB][8 * EDGE_DIM];
    int tid = threadIdx.x, warp = tid >> 5, lane = tid & 31;
    int eb = (blockIdx.x * WPB + warp) * 8;

    __half2 wc[EDGE_DIM];
    #pragma unroll
    for (int d = 0; d < EDGE_DIM; d++) {
        float2 w = *(const float2*)&Wc[d * H + 2 * lane];
        wc[d] = __floats2half2_rn(w.x, w.y);
    }
    float2 bc2 = *(const float2*)&bc[2 * lane];

    float* myEf = sEf[warp];
    for (int idx = lane; idx < 8 * EDGE_DIM; idx += 32)
        myEf[idx] = ef[(size_t)eb * EDGE_DIM + idx];
    int sidx = src[eb + (lane & 7)];
    int didx = dst[eb + (lane & 7)];
    __syncwarp();

    #pragma unroll
    for (int i = 0; i < 8; i++) {
        int s = __shfl_sync(0xffffffffu, sidx, i);
        int d = __shfl_sync(0xffffffffu, didx, i);
        float2 p2 = __half22float2(*(const __half2*)&P[s * 64 + 2 * lane]);
        float a0 = p2.x + bc2.x, a1 = p2.y + bc2.y;
        #pragma unroll
        for (int k = 0; k < EDGE_DIM; k++) {
            float e = myEf[i * EDGE_DIM + k];
            float2 w = __half22float2(wc[k]);
            a0 += e * w.x; a1 += e * w.y;
        }
        float o0 = lrelu(a0), o1 = lrelu(a1);
        *(__half2*)&h0[(size_t)(eb + i) * 64 + 2 * lane] = __floats2half2_rn(o0, o1);
        red_h2(&agg_out[d * 64 + 2 * lane], o0, o1);
    }
}

// ---------------- conv layer: HMMA, fp16 agg gather + scatter (R14 verbatim) ----------------
__global__ __launch_bounds__(256, 3) void conv_mma_kernel(
    const float* __restrict__ W, const float* __restrict__ bias,
    const int* __restrict__ src, const int* __restrict__ dst,
    const __half* __restrict__ agg_in, const __half* __restrict__ h_in,
    const __half* __restrict__ h0, __half* __restrict__ h_out,
    __half* __restrict__ agg_out) {
    __shared__ __align__(16) __half sW[64 * 72];
    __shared__ __align__(16) __half sT[8][16 * 72];

    int tid = threadIdx.x;
    for (int idx = tid; idx < 64 * 64; idx += 256) {
        int k = idx >> 6, n = idx & 63;
        sW[k * 72 + n] = __float2half_rn(W[idx]);
    }
    __syncthreads();
    int warp = tid >> 5, lane = tid & 31;
    float2 bias2 = *(const float2*)&bias[2 * lane];

    __half* myT = sT[warp];
    int base = ((blockIdx.x * 8 + warp) * CT) * 16;
    int am = lane >> 3;
    int arow = (am & 1) * 8 + (lane & 7);
    int acol0 = (am >> 1) * 8;

    for (int t = 0; t < CT; t++) {
        int eb = base + t * 16;
        int sidx = src[eb + (lane & 15)];
        int didx = dst[eb + (lane & 15)];
        #pragma unroll
        for (int i = 0; i < 16; i++) {
            int s = __shfl_sync(0xffffffffu, sidx, i);
            int r = (eb + i) ^ 1;
            float2 a = __half22float2(*(const __half2*)&agg_in[s * 64 + 2 * lane]);
            float2 hf = __half22float2(*(const __half2*)&h_in[r * 64 + 2 * lane]);
            *(__half2*)&myT[i * 72 + 2 * lane] = __floats2half2_rn(a.x - hf.x, a.y - hf.y);
        }
        __syncwarp();
        float acc[8][4];
        #pragma unroll
        for (int nt = 0; nt < 8; nt++) { acc[nt][0]=0.f; acc[nt][1]=0.f; acc[nt][2]=0.f; acc[nt][3]=0.f; }
        #pragma unroll
        for (int kh = 0; kh < 2; kh++) {
            unsigned a00, a01, a02, a03, a10, a11, a12, a13;
            unsigned addr0 = (unsigned)__cvta_generic_to_shared(&myT[arow * 72 + (2 * kh) * 16 + acol0]);
            LDMX4(a00, a01, a02, a03, addr0);
            unsigned addr1 = (unsigned)__cvta_generic_to_shared(&myT[arow * 72 + (2 * kh + 1) * 16 + acol0]);
            LDMX4(a10, a11, a12, a13, addr1);
            #pragma unroll
            for (int nt = 0; nt < 8; nt++) {
                unsigned b0, b1, b2, b3;
                unsigned addrB = (unsigned)__cvta_generic_to_shared(&sW[(kh * 32 + lane) * 72 + nt * 8]);
                LDMX4T(b0, b1, b2, b3, addrB);
                MMA16816(acc[nt], a00, a01, a02, a03, b0, b1);
                MMA16816(acc[nt], a10, a11, a12, a13, b2, b3);
            }
        }
        __syncwarp();
        int qrow = lane >> 2, qc = (lane & 3) * 2;
        #pragma unroll
        for (int nt = 0; nt < 8; nt++) {
            *(__half2*)&myT[qrow * 72 + nt * 8 + qc]       = __floats2half2_rn(acc[nt][0], acc[nt][1]);
            *(__half2*)&myT[(qrow + 8) * 72 + nt * 8 + qc] = __floats2half2_rn(acc[nt][2], acc[nt][3]);
        }
        __syncwarp();
        #pragma unroll
        for (int i = 0; i < 16; i++) {
            int d = __shfl_sync(0xffffffffu, didx, i);
            float2 m2  = __half22float2(*(const __half2*)&myT[i * 72 + 2 * lane]);
            float2 h0f = __half22float2(*(const __half2*)&h0[(eb + i) * 64 + 2 * lane]);
            float o0 = lrelu(h0f.x + bias2.x + m2.x);
            float o1 = lrelu(h0f.y + bias2.y + m2.y);
            *(__half2*)&h_out[(eb + i) * 64 + 2 * lane] = __floats2half2_rn(o0, o1);
            red_h2(&agg_out[d * 64 + 2 * lane], o0, o1);
        }
        __syncwarp();
    }
}

// ---------------- readout via HMMA: gpool[gid[n]] += lrelu([node,agg]@Wa + ba) ----------------
__global__ __launch_bounds__(256, 3) void readout_mma_kernel(
    const __half* __restrict__ node, const __half* __restrict__ agg,
    const float* __restrict__ Wa, const float* __restrict__ ba,
    const int* __restrict__ gid, float* __restrict__ gpool) {
    __shared__ __align__(16) __half sW[128 * 72];
    __shared__ __align__(16) __half sT[8][16 * 72];
    __shared__ float sba[64];

    int tid = threadIdx.x;
    for (int idx = tid; idx < 128 * 64; idx += 256) {
        int k = idx >> 6, n = idx & 63;
        sW[k * 72 + n] = __float2half_rn(Wa[k * H + n]);
    }
    if (tid < 64) sba[tid] = ba[tid];
    __syncthreads();
    int warp = tid >> 5, lane = tid & 31;

    __half* myT = sT[warp];
    int base = ((blockIdx.x * 8 + warp) * CT) * 16;
    int am = lane >> 3;
    int arow = (am & 1) * 8 + (lane & 7);
    int acol0 = (am >> 1) * 8;

    for (int t = 0; t < CT; t++) {
        int nb = base + t * 16;
        int gidx = gid[nb + (lane & 15)];
        float acc[8][4];
        #pragma unroll
        for (int nt = 0; nt < 8; nt++) { acc[nt][0]=0.f; acc[nt][1]=0.f; acc[nt][2]=0.f; acc[nt][3]=0.f; }

        #pragma unroll
        for (int stage = 0; stage < 2; stage++) {
            #pragma unroll
            for (int i = 0; i < 16; i++) {
                const __half* in = stage ? &agg[(nb + i) * 64] : &node[(nb + i) * 64];
                *(__half2*)&myT[i * 72 + 2 * lane] = *(const __half2*)&in[2 * lane];
            }
            __syncwarp();
            #pragma unroll
            for (int kh = 0; kh < 2; kh++) {
                unsigned a00, a01, a02, a03, a10, a11, a12, a13;
                unsigned addr0 = (unsigned)__cvta_generic_to_shared(&myT[arow * 72 + (2 * kh) * 16 + acol0]);
                LDMX4(a00, a01, a02, a03, addr0);
                unsigned addr1 = (unsigned)__cvta_generic_to_shared(&myT[arow * 72 + (2 * kh + 1) * 16 + acol0]);
                LDMX4(a10, a11, a12, a13, addr1);
                #pragma unroll
                for (int nt = 0; nt < 8; nt++) {
                    unsigned b0, b1, b2, b3;
                    unsigned addrB = (unsigned)__cvta_generic_to_shared(
                        &sW[(stage * 64 + kh * 32 + lane) * 72 + nt * 8]);
                    LDMX4T(b0, b1, b2, b3, addrB);
                    MMA16816(acc[nt], a00, a01, a02, a03, b0, b1);
                    MMA16816(acc[nt], a10, a11, a12, a13, b2, b3);
                }
            }
            __syncwarp();
        }
        int qrow = lane >> 2, qc = (lane & 3) * 2;
        int g0 = __shfl_sync(0xffffffffu, gidx, qrow);
        int g1 = __shfl_sync(0xffffffffu, gidx, qrow + 8);
        #pragma unroll
        for (int nt = 0; nt < 8; nt++) {
            float b0 = sba[nt * 8 + qc], b1 = sba[nt * 8 + qc + 1];
            float o00 = lrelu(acc[nt][0] + b0), o01 = lrelu(acc[nt][1] + b1);
            float o10 = lrelu(acc[nt][2] + b0), o11 = lrelu(acc[nt][3] + b1);
            asm volatile("red.global.add.v2.f32 [%0], {%1, %2};"
                         :: "l"(&gpool[g0 * 64 + nt * 8 + qc]), "f"(o00), "f"(o01) : "memory");
            asm volatile("red.global.add.v2.f32 [%0], {%1, %2};"
                         :: "l"(&gpool[g1 * 64 + nt * 8 + qc]), "f"(o10), "f"(o11) : "memory");
        }
    }
}

// ---------------- head ----------------
__global__ __launch_bounds__(256) void head_kernel(
    const float* __restrict__ g, const float* __restrict__ W1,
    const float* __restrict__ b1, const float* __restrict__ W2,
    const float* __restrict__ b2, float* __restrict__ out) {
    __shared__ float2 sW[H * 32];
    __shared__ float sb[H];
    __shared__ float sW2[H];
    for (int idx = threadIdx.x; idx < H * 32; idx += 256) {
        int k = idx >> 5, j = idx & 31;
        sW[idx] = make_float2(W1[k * H + j], W1[k * H + j + 32]);
    }
    if (threadIdx.x < H) { sb[threadIdx.x] = b1[threadIdx.x]; sW2[threadIdx.x] = W2[threadIdx.x]; }
    __syncthreads();
    int warp = threadIdx.x >> 5, lane = threadIdx.x & 31;
    int gi = blockIdx.x * 8 + warp;
    const float* row = g + gi * H;
    float f0 = row[lane], f1 = row[lane + 32];
    float a0 = sb[lane], a1 = sb[lane + 32];
    #pragma unroll
    for (int k = 0; k < H; k++) {
        float fk = __shfl_sync(0xffffffffu, (k < 32 ? f0 : f1), k & 31);
        float2 w = sW[k * 32 + lane];
        a0 += fk * w.x; a1 += fk * w.y;
    }
    a0 = lrelu(a0); a1 = lrelu(a1);
    float p = a0 * sW2[lane] + a1 * sW2[lane + 32];
    #pragma unroll
    for (int o = 16; o; o >>= 1) p += __shfl_xor_sync(0xffffffffu, p, o);
    if (lane == 0) out[gi] = p + b2[0];
}

// ---------------- launch ----------------
extern "C" void kernel_launch(void* const* d_in, const int* in_sizes, int n_in,
                              void* d_out, int out_size) {
    const float* node_feats = (const float*)d_in[0];
    const float* edge_feats = (const float*)d_in[1];
    const int*   src        = (const int*)d_in[2];
    const int*   dst        = (const int*)d_in[3];
    const int*   gid        = (const int*)d_in[4];
    const float* Wn = (const float*)d_in[5];
    const float* bn = (const float*)d_in[6];
    const float* We = (const float*)d_in[7];
    const float* be = (const float*)d_in[8];
    const float* Wi = (const float*)d_in[9];
    const float* bi = (const float*)d_in[10];
    const float* Wa = (const float*)d_in[11];
    const float* ba = (const float*)d_in[12];
    const float* Wl = (const float*)d_in[13];
    const float* bl = (const float*)d_in[14];
    const float* W1 = (const float*)d_in[15];
    const float* b1 = (const float*)d_in[16];
    const float* W2 = (const float*)d_in[17];
    const float* b2 = (const float*)d_in[18];
    float* out = (float*)d_out;

    __half *p_node, *p_P, *p_h0, *p_hA, *p_hB, *p_aggA, *p_aggB;
    float *p_gpool, *p_Wc, *p_bc;
    cudaGetSymbolAddress((void**)&p_node, g_node);
    cudaGetSymbolAddress((void**)&p_P, g_P);
    cudaGetSymbolAddress((void**)&p_h0, g_h0);
    cudaGetSymbolAddress((void**)&p_hA, g_hA);
    cudaGetSymbolAddress((void**)&p_hB, g_hB);
    cudaGetSymbolAddress((void**)&p_aggA, g_aggA);
    cudaGetSymbolAddress((void**)&p_aggB, g_aggB);
    cudaGetSymbolAddress((void**)&p_gpool, g_gpool);
    cudaGetSymbolAddress((void**)&p_Wc, g_Wc);
    cudaGetSymbolAddress((void**)&p_bc, g_bc);

    const size_t aggBytes = (size_t)N_NODES * H * sizeof(__half);

    prep_kernel<<<4, 256>>>(We, be, Wi, bi, p_Wc, p_bc);
    node_proj_mma_kernel<<<PGRID, 256>>>(node_feats, Wn, bn, p_node);
    pmma_kernel<<<PGRID, 256>>>(p_node, Wi, p_P);

    cudaMemsetAsync(p_aggA, 0, aggBytes);
    h0_lite_kernel<<<H0GRID, 256>>>(p_P, edge_feats, src, dst, p_Wc, p_bc,
                                    p_h0, p_aggA);

    cudaMemsetAsync(p_aggB, 0, aggBytes);
    conv_mma_kernel<<<CGRID, 256>>>(Wl + 0 * H * H, bl + 0 * H, src, dst,
                                    p_aggA, p_h0, p_h0, p_hA, p_aggB);
    cudaMemsetAsync(p_aggA, 0, aggBytes);
    conv_mma_kernel<<<CGRID, 256>>>(Wl + 1 * H * H, bl + 1 * H, src, dst,
                                    p_aggB, p_hA, p_h0, p_hB, p_aggA);
    cudaMemsetAsync(p_aggB, 0, aggBytes);
    conv_mma_kernel<<<CGRID, 256>>>(Wl + 2 * H * H, bl + 2 * H, src, dst,
                                    p_aggA, p_hB, p_h0, p_hA, p_aggB);
    cudaMemsetAsync(p_aggA, 0, aggBytes);
    conv_mma_kernel<<<CGRID, 256>>>(Wl + 3 * H * H, bl + 3 * H, src, dst,
                                    p_aggB, p_hA, p_h0, p_hB, p_aggA);

    cudaMemsetAsync(p_gpool, 0, (size_t)N_GRAPHS * H * sizeof(float));
    readout_mma_kernel<<<PGRID, 256>>>(p_node, p_aggA, Wa, ba, gid, p_gpool);
    head_kernel<<<N_GRAPHS / 8, 256>>>(p_gpool, W1, b1, W2, b2, out);
}